// round 8
// baseline (speedup 1.0000x reference)
#include <cuda_runtime.h>

#define T_    1024
#define D_    2048
#define DFF_  1024
#define E_    16
#define K_    6
#define BM    128
#define NSLOT (T_ * K_)                 /* 6144 */
#define MAXROWS (NSLOT + E_ * BM)       /* 8192 */
#define MAXTILES (MAXROWS / BM)         /* 64   */

// Static device scratch (no runtime allocation allowed).
// g_H as float4 => guaranteed 16B alignment for STG.128/LDG.128.
__device__ int    g_tok[MAXROWS];
__device__ float  g_wt[MAXROWS];
__device__ int    g_tile_expert[MAXTILES];
__device__ int    g_tile_mstart[MAXTILES];
__device__ float4 g_H4[(size_t)MAXROWS * DFF_ / 4];   // 33.5 MB SwiGLU intermediate

// ---------------------------------------------------------------------------
// Setup: bucket (token, weight) slots by expert, pad segments to BM, build
// a fixed-size tile table. Single block, fully synchronized internally.
// Sniffs whether `sel` is int32 or int64: reads first 32 slots as int64;
// any out-of-range value => buffer is int32 (ids in [0,16) make the int64
// interpretation of an int32 buffer out-of-range w.p. 1 - 16^-32).
// ---------------------------------------------------------------------------
__global__ void setup_kernel(const void* __restrict__ sel_raw,
                             const float* __restrict__ rw) {
    __shared__ int cnt[E_], pos[E_];
    __shared__ int padded_total;
    __shared__ int is32;
    int tid = threadIdx.x;

    if (tid == 0) {
        const long long* s64 = (const long long*)sel_raw;
        int bad = 0;
        for (int i = 0; i < 32; i++) {
            long long v = s64[i];
            if (v < 0 || v >= E_) bad++;
        }
        is32 = (bad > 0) ? 1 : 0;
    }
    if (tid < E_) cnt[tid] = 0;
    __syncthreads();

    const int*       s32 = (const int*)sel_raw;
    const long long* s64 = (const long long*)sel_raw;
    int use32 = is32;

    for (int i = tid; i < NSLOT; i += blockDim.x) {
        int e = use32 ? s32[i] : (int)s64[i];
        if (e >= 0 && e < E_) atomicAdd(&cnt[e], 1);
    }
    __syncthreads();

    if (tid == 0) {
        int off = 0, tI = 0;
        for (int e = 0; e < E_; e++) {
            pos[e] = off;
            int nt = (cnt[e] + BM - 1) / BM;
            for (int j = 0; j < nt && tI < MAXTILES; j++) {
                g_tile_expert[tI] = e;
                g_tile_mstart[tI] = off + j * BM;
                tI++;
            }
            off += nt * BM;
        }
        padded_total = (off <= MAXROWS) ? off : MAXROWS;
        for (; tI < MAXTILES; tI++) { g_tile_expert[tI] = -1; g_tile_mstart[tI] = 0; }
    }
    __syncthreads();

    int tot = padded_total;
    for (int i = tid; i < tot; i += blockDim.x) {
        g_tok[i] = 0;
        g_wt[i]  = 0.0f;   // zero weight => exactly zero contribution
    }
    __syncthreads();

    for (int i = tid; i < NSLOT; i += blockDim.x) {
        int e = use32 ? s32[i] : (int)s64[i];
        if (e < 0 || e >= E_) continue;
        int p = atomicAdd(&pos[e], 1);
        if (p < MAXROWS) {
            g_tok[p] = i / K_;
            g_wt[p]  = rw[i];
        }
    }
}

// ---------------------------------------------------------------------------
// GEMM1: H[r, :] = silu(s0*(x[tok[r]] @ W0e^T)) * (s1*(x[tok[r]] @ W1e^T))
// Tiles: 128(M) x 64(N) x 16(K), 256 threads, 8x4 microtile for BOTH G and U.
// ---------------------------------------------------------------------------
__global__ __launch_bounds__(256)
void gemm1_kernel(const float* __restrict__ x,
                  const float* __restrict__ w0,
                  const float* __restrict__ w1,
                  const float* __restrict__ s0,
                  const float* __restrict__ s1) {
    int e = g_tile_expert[blockIdx.y];
    if (e < 0) return;
    int m0 = g_tile_mstart[blockIdx.y];
    int n0 = blockIdx.x * 64;

    __shared__ float As [16][132];   // [k][m], row stride 528B (16B multiple)
    __shared__ float Bs0[16][68];    // [k][n], row stride 272B (16B multiple)
    __shared__ float Bs1[16][68];
    __shared__ int   rowtok[BM];

    int tid = threadIdx.x;
    if (tid < BM) rowtok[tid] = g_tok[m0 + tid];
    __syncthreads();

    const float* w0e = w0 + (size_t)e * DFF_ * D_;
    const float* w1e = w1 + (size_t)e * DFF_ * D_;
    float* gH = (float*)g_H4;

    int tx = tid & 15;   // 16 cols of 4  -> 64 N
    int ty = tid >> 4;   // 16 rows of 8  -> 128 M

    float accg[8][4] = {};
    float accu[8][4] = {};

    for (int k0 = 0; k0 < D_; k0 += 16) {
        // A: 128x16 = 512 float4, 2 per thread (gathered rows of x)
        #pragma unroll
        for (int it = 0; it < 2; it++) {
            int f  = tid + 256 * it;
            int m  = f >> 2;
            int k4 = (f & 3) * 4;
            float4 v = *(const float4*)(x + (size_t)rowtok[m] * D_ + k0 + k4);
            As[k4 + 0][m] = v.x; As[k4 + 1][m] = v.y;
            As[k4 + 2][m] = v.z; As[k4 + 3][m] = v.w;
        }
        // B0 / B1: 64x16 = 256 float4 each, 1 per thread
        {
            int n  = tid >> 2;
            int k4 = (tid & 3) * 4;
            float4 v0 = *(const float4*)(w0e + (size_t)(n0 + n) * D_ + k0 + k4);
            Bs0[k4 + 0][n] = v0.x; Bs0[k4 + 1][n] = v0.y;
            Bs0[k4 + 2][n] = v0.z; Bs0[k4 + 3][n] = v0.w;
            float4 v1 = *(const float4*)(w1e + (size_t)(n0 + n) * D_ + k0 + k4);
            Bs1[k4 + 0][n] = v1.x; Bs1[k4 + 1][n] = v1.y;
            Bs1[k4 + 2][n] = v1.z; Bs1[k4 + 3][n] = v1.w;
        }
        __syncthreads();

        #pragma unroll
        for (int kk = 0; kk < 16; kk++) {
            float a[8];
            float4 a0 = *(const float4*)&As[kk][ty * 8];
            float4 a1 = *(const float4*)&As[kk][ty * 8 + 4];
            a[0] = a0.x; a[1] = a0.y; a[2] = a0.z; a[3] = a0.w;
            a[4] = a1.x; a[5] = a1.y; a[6] = a1.z; a[7] = a1.w;
            float4 b0 = *(const float4*)&Bs0[kk][tx * 4];
            float4 b1 = *(const float4*)&Bs1[kk][tx * 4];
            float bg[4] = {b0.x, b0.y, b0.z, b0.w};
            float bu[4] = {b1.x, b1.y, b1.z, b1.w};
            #pragma unroll
            for (int i = 0; i < 8; i++)
                #pragma unroll
                for (int j = 0; j < 4; j++) {
                    accg[i][j] += a[i] * bg[j];
                    accu[i][j] += a[i] * bu[j];
                }
        }
        __syncthreads();
    }

    float s0e = s0[e], s1e = s1[e];
    #pragma unroll
    for (int i = 0; i < 8; i++) {
        int r = m0 + ty * 8 + i;
        float h[4];
        #pragma unroll
        for (int j = 0; j < 4; j++) {
            float g = accg[i][j] * s0e;
            float u = accu[i][j] * s1e;
            h[j] = g / (1.0f + __expf(-g)) * u;   // silu(g) * u
        }
        float4 hv = make_float4(h[0], h[1], h[2], h[3]);
        *(float4*)&gH[(size_t)r * DFF_ + n0 + tx * 4] = hv;
    }
}

// ---------------------------------------------------------------------------
// GEMM2: y[r, :] = H[r] @ W2e^T ; out[tok[r], :] += w[r] * s2e * y[r, :]
// Tiles: 128 x 128 x 16, 256 threads, 8x8 microtile, atomic scatter-add.
// ---------------------------------------------------------------------------
__global__ __launch_bounds__(256)
void gemm2_kernel(const float* __restrict__ w2,
                  const float* __restrict__ s2,
                  float* __restrict__ out) {
    int e = g_tile_expert[blockIdx.y];
    if (e < 0) return;
    int m0 = g_tile_mstart[blockIdx.y];
    int n0 = blockIdx.x * 128;

    __shared__ float As[16][132];
    __shared__ float Bs[16][132];

    int tid = threadIdx.x;
    int tx = tid & 15;   // 16 cols of 8 -> 128 N
    int ty = tid >> 4;   // 16 rows of 8 -> 128 M

    const float* w2e = w2 + (size_t)e * D_ * DFF_;
    const float* gH = (const float*)g_H4;
    float acc[8][8] = {};

    for (int k0 = 0; k0 < DFF_; k0 += 16) {
        #pragma unroll
        for (int it = 0; it < 2; it++) {
            int f  = tid + 256 * it;
            int m  = f >> 2;
            int k4 = (f & 3) * 4;
            float4 va = *(const float4*)(gH + (size_t)(m0 + m) * DFF_ + k0 + k4);
            As[k4 + 0][m] = va.x; As[k4 + 1][m] = va.y;
            As[k4 + 2][m] = va.z; As[k4 + 3][m] = va.w;
            float4 vb = *(const float4*)(w2e + (size_t)(n0 + m) * DFF_ + k0 + k4);
            Bs[k4 + 0][m] = vb.x; Bs[k4 + 1][m] = vb.y;
            Bs[k4 + 2][m] = vb.z; Bs[k4 + 3][m] = vb.w;
        }
        __syncthreads();

        #pragma unroll
        for (int kk = 0; kk < 16; kk++) {
            float a[8], b[8];
            float4 a0 = *(const float4*)&As[kk][ty * 8];
            float4 a1 = *(const float4*)&As[kk][ty * 8 + 4];
            a[0] = a0.x; a[1] = a0.y; a[2] = a0.z; a[3] = a0.w;
            a[4] = a1.x; a[5] = a1.y; a[6] = a1.z; a[7] = a1.w;
            float4 b0 = *(const float4*)&Bs[kk][tx * 8];
            float4 b1 = *(const float4*)&Bs[kk][tx * 8 + 4];
            b[0] = b0.x; b[1] = b0.y; b[2] = b0.z; b[3] = b0.w;
            b[4] = b1.x; b[5] = b1.y; b[6] = b1.z; b[7] = b1.w;
            #pragma unroll
            for (int i = 0; i < 8; i++)
                #pragma unroll
                for (int j = 0; j < 8; j++)
                    acc[i][j] += a[i] * b[j];
        }
        __syncthreads();
    }

    float s2e = s2[e];
    #pragma unroll
    for (int i = 0; i < 8; i++) {
        int r = m0 + ty * 8 + i;
        float w = g_wt[r];
        if (w == 0.0f) continue;      // padded row
        int t = g_tok[r];
        float c = w * s2e;
        #pragma unroll
        for (int j = 0; j < 8; j++)
            atomicAdd(&out[(size_t)t * D_ + n0 + tx * 8 + j], c * acc[i][j]);
    }
}

// ---------------------------------------------------------------------------
extern "C" void kernel_launch(void* const* d_in, const int* in_sizes, int n_in,
                              void* d_out, int out_size) {
    const float* x   = (const float*)d_in[0];
    const float* w0  = (const float*)d_in[1];
    const float* w1  = (const float*)d_in[2];
    const float* w2  = (const float*)d_in[3];
    const float* s0  = (const float*)d_in[4];
    const float* s1  = (const float*)d_in[5];
    const float* s2  = (const float*)d_in[6];
    const void*  sel = (const void*)d_in[7];
    const float* rw  = (const float*)d_in[8];
    float* out = (float*)d_out;

    cudaMemsetAsync(out, 0, (size_t)out_size * sizeof(float));
    setup_kernel<<<1, 256>>>(sel, rw);
    gemm1_kernel<<<dim3(DFF_ / 64, MAXTILES), 256>>>(x, w0, w1, s0, s1);
    gemm2_kernel<<<dim3(D_ / 128, MAXTILES), 256>>>(w2, s2, out);
}

// round 13
// speedup vs baseline: 2.7832x; 2.7832x over previous
#include <cuda_runtime.h>
#include <cstdint>

#define T_    1024
#define D_    2048
#define DFF_  1024
#define E_    16
#define K_    6
#define BM    128
#define NSLOT 6144
#define MAXROWS 8192
#define MAXTILES 64
#define BK    32
#define NSTAGE 3
#define APITCH 36                         /* padded floats per smem row */
#define STAGE_FLOATS (256 * APITCH)       /* 256 rows * 36 = 9216 floats */
#define SMEM_BYTES (512 + NSTAGE * STAGE_FLOATS * 4)   /* 111104 */

// Static device scratch (no runtime allocation allowed)
__device__ int    g_tok[MAXROWS];
__device__ float  g_wt[MAXROWS];
__device__ int    g_slotrow[NSLOT];
__device__ int    g_tile_expert[MAXTILES];
__device__ int    g_tile_mstart[MAXTILES];
__device__ float4 g_H4[(size_t)MAXROWS * DFF_ / 4];  // SwiGLU intermediate (33.5 MB)
__device__ float4 g_Y4[(size_t)MAXROWS * D_ / 4];    // per-slot scaled output (67 MB)

// ---------------------------------------------------------------------------
__device__ __forceinline__ uint32_t smem_u32(const void* p) {
    uint32_t a;
    asm("{ .reg .u64 t; cvta.to.shared.u64 t, %1; cvt.u32.u64 %0, t; }" : "=r"(a) : "l"(p));
    return a;
}
__device__ __forceinline__ void cp_async16(uint32_t dst, const void* src) {
    asm volatile("cp.async.cg.shared.global [%0], [%1], 16;" :: "r"(dst), "l"(src));
}
__device__ __forceinline__ void cp_commit() {
    asm volatile("cp.async.commit_group;" ::: "memory");
}
__device__ __forceinline__ uint32_t f2tf(float f) {   // round-to-nearest tf32
    uint32_t r;
    asm("cvt.rna.tf32.f32 %0, %1;" : "=r"(r) : "f"(f));
    return r;
}
#define MMA_TF32(c, a, b) \
    asm volatile("mma.sync.aligned.m16n8k8.row.col.f32.tf32.tf32.f32 " \
                 "{%0,%1,%2,%3},{%4,%5,%6,%7},{%8,%9},{%0,%1,%2,%3};" \
                 : "+f"((c)[0]), "+f"((c)[1]), "+f"((c)[2]), "+f"((c)[3]) \
                 : "r"((a)[0]), "r"((a)[1]), "r"((a)[2]), "r"((a)[3]), \
                   "r"((b)[0]), "r"((b)[1]))

// ---------------------------------------------------------------------------
// Setup (validated scaffold): bucket slots by expert, pad to BM, tile table,
// slot->row map. int32/int64 dtype sniff (confirmed int32 in R8).
// ---------------------------------------------------------------------------
__global__ void setup_kernel(const void* __restrict__ sel_raw,
                             const float* __restrict__ rw) {
    __shared__ int cnt[E_], pos[E_];
    __shared__ int padded_total;
    __shared__ int is32;
    int tid = threadIdx.x, lane = tid & 31;

    if (tid == 0) {
        const long long* s64 = (const long long*)sel_raw;
        int bad = 0;
        for (int i = 0; i < 32; i++) {
            long long v = s64[i];
            if (v < 0 || v >= E_) bad++;
        }
        is32 = (bad > 0) ? 1 : 0;
    }
    if (tid < E_) cnt[tid] = 0;
    __syncthreads();

    const int*       s32 = (const int*)sel_raw;
    const long long* s64 = (const long long*)sel_raw;
    int use32 = is32;

    for (int i = tid; i < NSLOT; i += 256) {
        int e = use32 ? s32[i] : (int)s64[i];
        e = max(0, min(E_ - 1, e));
        unsigned m = __match_any_sync(0xffffffffu, e);
        if (lane == __ffs(m) - 1) atomicAdd(&cnt[e], __popc(m));
    }
    __syncthreads();

    if (tid == 0) {
        int off = 0, tI = 0;
        for (int e = 0; e < E_; e++) {
            pos[e] = off;
            int nt = (cnt[e] + BM - 1) / BM;
            for (int j = 0; j < nt && tI < MAXTILES; j++) {
                g_tile_expert[tI] = e;
                g_tile_mstart[tI] = off + j * BM;
                tI++;
            }
            off += nt * BM;
        }
        padded_total = (off <= MAXROWS) ? off : MAXROWS;
        for (; tI < MAXTILES; tI++) { g_tile_expert[tI] = -1; g_tile_mstart[tI] = 0; }
    }
    __syncthreads();

    int tot = padded_total;
    for (int i = tid; i < tot; i += 256) {
        g_tok[i] = 0;
        g_wt[i]  = 0.0f;
    }
    __syncthreads();

    for (int i = tid; i < NSLOT; i += 256) {
        int e = use32 ? s32[i] : (int)s64[i];
        e = max(0, min(E_ - 1, e));
        unsigned m = __match_any_sync(0xffffffffu, e);
        int leader = __ffs(m) - 1;
        int base;
        if (lane == leader) base = atomicAdd(&pos[e], __popc(m));
        base = __shfl_sync(0xffffffffu, base, leader);
        int p = base + __popc(m & ((1u << lane) - 1));
        g_tok[p] = i / K_;
        g_wt[p]  = rw[i];
        g_slotrow[i] = p;
    }
}

// ---------------------------------------------------------------------------
// GEMM1 (mma.sync tf32): gate[128,64] & up[128,64] in one pass; SwiGLU -> H.
// 256 thr = 8 warps as 4(M) x 2(N); warp: 32M x 32N per matrix.
// ---------------------------------------------------------------------------
__global__ __launch_bounds__(256)
void gemm1_mma(const float* __restrict__ x,  const float* __restrict__ w0,
               const float* __restrict__ w1, const float* __restrict__ s0,
               const float* __restrict__ s1) {
    int e = g_tile_expert[blockIdx.y];
    if (e < 0) return;
    extern __shared__ float smf[];
    int* rowtok = (int*)smf;                  // 128 ints
    float* stg = smf + 128;                   // stage base (512B offset)
    int tid = threadIdx.x, lane = tid & 31, wid = tid >> 5;
    int wm = wid >> 1, wn = wid & 1;
    int g = lane >> 2, t = lane & 3;
    int m0 = g_tile_mstart[blockIdx.y];
    int n0 = blockIdx.x * 64;
    const float* w0e = w0 + (size_t)e * DFF_ * D_;
    const float* w1e = w1 + (size_t)e * DFF_ * D_;

    if (tid < 128) rowtok[tid] = g_tok[m0 + tid];
    __syncthreads();

    float cg[2][4][4] = {};
    float cu[2][4][4] = {};

    auto load_chunk = [&](int c) {
        int st = c % NSTAGE;
        float* As = stg + st * STAGE_FLOATS;
        float* B0 = As + 128 * APITCH;
        float* B1 = B0 + 64 * APITCH;
        int k0 = c * BK;
#pragma unroll
        for (int i = 0; i < 4; i++) {         // A: 128 rows x 8 chunks
            int idx = tid + 256 * i;
            int row = idx >> 3, c4 = idx & 7;
            cp_async16(smem_u32(As + row * APITCH + c4 * 4),
                       x + (size_t)rowtok[row] * D_ + k0 + c4 * 4);
        }
#pragma unroll
        for (int i = 0; i < 4; i++) {         // B0,B1: 64 rows x 8 chunks each
            int idx = tid + 256 * i;
            int row = (idx >> 3) & 63, c4 = idx & 7;
            const float* src = (idx < 512) ? (w0e + (size_t)(n0 + row) * D_)
                                           : (w1e + (size_t)(n0 + row) * D_);
            float* dst = (idx < 512) ? B0 : B1;
            cp_async16(smem_u32(dst + row * APITCH + c4 * 4), src + k0 + c4 * 4);
        }
        cp_commit();
    };

    load_chunk(0); load_chunk(1); load_chunk(2);

    const int NCH = D_ / BK;                  // 64
    for (int c = 0; c < NCH; c++) {
        asm volatile("cp.async.wait_group 2;" ::: "memory");
        __syncthreads();
        const float* As = stg + (c % NSTAGE) * STAGE_FLOATS;
        const float* B0 = As + 128 * APITCH;
        const float* B1 = B0 + 64 * APITCH;
#pragma unroll
        for (int ks = 0; ks < 4; ks++) {
            int k = ks * 8;
            uint32_t a[2][4];
#pragma unroll
            for (int mi = 0; mi < 2; mi++) {
                int r = wm * 32 + mi * 16;
                a[mi][0] = f2tf(As[(r + g)     * APITCH + k + t]);
                a[mi][1] = f2tf(As[(r + g + 8) * APITCH + k + t]);
                a[mi][2] = f2tf(As[(r + g)     * APITCH + k + t + 4]);
                a[mi][3] = f2tf(As[(r + g + 8) * APITCH + k + t + 4]);
            }
#pragma unroll
            for (int ni = 0; ni < 4; ni++) {
                int n = wn * 32 + ni * 8;
                uint32_t bg[2], bu[2];
                bg[0] = f2tf(B0[(n + g) * APITCH + k + t]);
                bg[1] = f2tf(B0[(n + g) * APITCH + k + t + 4]);
                bu[0] = f2tf(B1[(n + g) * APITCH + k + t]);
                bu[1] = f2tf(B1[(n + g) * APITCH + k + t + 4]);
#pragma unroll
                for (int mi = 0; mi < 2; mi++) {
                    MMA_TF32(cg[mi][ni], a[mi], bg);
                    MMA_TF32(cu[mi][ni], a[mi], bu);
                }
            }
        }
        __syncthreads();
        if (c + NSTAGE < NCH) load_chunk(c + NSTAGE);
        else cp_commit();                     // empty group: keeps wait_group 2 == "stage c done"
    }

    float s0e = s0[e], s1e = s1[e];
    float* gH = (float*)g_H4;
#pragma unroll
    for (int mi = 0; mi < 2; mi++) {
#pragma unroll
        for (int ni = 0; ni < 4; ni++) {
            int col = n0 + wn * 32 + ni * 8 + 2 * t;
            int r0 = m0 + wm * 32 + mi * 16 + g;
            float gv0 = cg[mi][ni][0] * s0e, uv0 = cu[mi][ni][0] * s1e;
            float gv1 = cg[mi][ni][1] * s0e, uv1 = cu[mi][ni][1] * s1e;
            float gv2 = cg[mi][ni][2] * s0e, uv2 = cu[mi][ni][2] * s1e;
            float gv3 = cg[mi][ni][3] * s0e, uv3 = cu[mi][ni][3] * s1e;
            float2 h0 = make_float2(gv0 / (1.0f + __expf(-gv0)) * uv0,
                                    gv1 / (1.0f + __expf(-gv1)) * uv1);
            float2 h1 = make_float2(gv2 / (1.0f + __expf(-gv2)) * uv2,
                                    gv3 / (1.0f + __expf(-gv3)) * uv3);
            *(float2*)(gH + (size_t)r0 * DFF_ + col)       = h0;
            *(float2*)(gH + (size_t)(r0 + 8) * DFF_ + col) = h1;
        }
    }
}

// ---------------------------------------------------------------------------
// GEMM2 (mma.sync tf32): Y[128,128] = H[128,1024] @ W2tile^T, scaled wt*s2.
// 8 warps 4(M) x 2(N); warp: 32M x 64N.
// ---------------------------------------------------------------------------
__global__ __launch_bounds__(256)
void gemm2_mma(const float* __restrict__ w2, const float* __restrict__ s2) {
    int e = g_tile_expert[blockIdx.y];
    if (e < 0) return;
    extern __shared__ float smf[];
    float* stg = smf + 128;
    int tid = threadIdx.x, lane = tid & 31, wid = tid >> 5;
    int wm = wid >> 1, wn = wid & 1;
    int g = lane >> 2, t = lane & 3;
    int m0 = g_tile_mstart[blockIdx.y];
    int n0 = blockIdx.x * 128;
    const float* w2e = w2 + (size_t)e * D_ * DFF_;
    const float* gH  = (const float*)g_H4;

    float acc[2][8][4] = {};

    auto load_chunk = [&](int c) {
        int st = c % NSTAGE;
        float* As = stg + st * STAGE_FLOATS;
        float* Bs = As + 128 * APITCH;
        int k0 = c * BK;
#pragma unroll
        for (int i = 0; i < 4; i++) {
            int idx = tid + 256 * i;
            int row = idx >> 3, c4 = idx & 7;
            cp_async16(smem_u32(As + row * APITCH + c4 * 4),
                       gH + (size_t)(m0 + row) * DFF_ + k0 + c4 * 4);
        }
#pragma unroll
        for (int i = 0; i < 4; i++) {
            int idx = tid + 256 * i;
            int row = idx >> 3, c4 = idx & 7;
            cp_async16(smem_u32(Bs + row * APITCH + c4 * 4),
                       w2e + (size_t)(n0 + row) * DFF_ + k0 + c4 * 4);
        }
        cp_commit();
    };

    load_chunk(0); load_chunk(1); load_chunk(2);

    const int NCH = DFF_ / BK;                // 32
    for (int c = 0; c < NCH; c++) {
        asm volatile("cp.async.wait_group 2;" ::: "memory");
        __syncthreads();
        const float* As = stg + (c % NSTAGE) * STAGE_FLOATS;
        const float* Bs = As + 128 * APITCH;
#pragma unroll
        for (int ks = 0; ks < 4; ks++) {
            int k = ks * 8;
            uint32_t a[2][4];
#pragma unroll
            for (int mi = 0; mi < 2; mi++) {
                int r = wm * 32 + mi * 16;
                a[mi][0] = f2tf(As[(r + g)     * APITCH + k + t]);
                a[mi][1] = f2tf(As[(r + g + 8) * APITCH + k + t]);
                a[mi][2] = f2tf(As[(r + g)     * APITCH + k + t + 4]);
                a[mi][3] = f2tf(As[(r + g + 8) * APITCH + k + t + 4]);
            }
#pragma unroll
            for (int ni = 0; ni < 8; ni++) {
                int n = wn * 64 + ni * 8;
                uint32_t b[2];
                b[0] = f2tf(Bs[(n + g) * APITCH + k + t]);
                b[1] = f2tf(Bs[(n + g) * APITCH + k + t + 4]);
#pragma unroll
                for (int mi = 0; mi < 2; mi++)
                    MMA_TF32(acc[mi][ni], a[mi], b);
            }
        }
        __syncthreads();
        if (c + NSTAGE < NCH) load_chunk(c + NSTAGE);
        else cp_commit();                     // empty group (tail correctness)
    }

    float s2e = s2[e];
    float* gY = (float*)g_Y4;
#pragma unroll
    for (int mi = 0; mi < 2; mi++) {
        int r0 = m0 + wm * 32 + mi * 16 + g;
        float coef0 = g_wt[r0] * s2e;
        float coef1 = g_wt[r0 + 8] * s2e;
#pragma unroll
        for (int ni = 0; ni < 8; ni++) {
            int col = n0 + wn * 64 + ni * 8 + 2 * t;
            float2 v0 = make_float2(coef0 * acc[mi][ni][0], coef0 * acc[mi][ni][1]);
            float2 v1 = make_float2(coef1 * acc[mi][ni][2], coef1 * acc[mi][ni][3]);
            *(float2*)(gY + (size_t)r0 * D_ + col)       = v0;
            *(float2*)(gY + (size_t)(r0 + 8) * D_ + col) = v1;
        }
    }
}

// ---------------------------------------------------------------------------
// Reduce: out[t,:] = sum over the token's 6 slot rows of Y (fixed order).
// ---------------------------------------------------------------------------
__global__ __launch_bounds__(256)
void reduce_kernel(float4* __restrict__ out) {
    int idx = blockIdx.x * 256 + threadIdx.x;
    int t  = idx >> 9;                        // D_/4 = 512
    int c4 = idx & 511;
    const int* sr = g_slotrow + t * K_;
    float4 acc = make_float4(0.f, 0.f, 0.f, 0.f);
#pragma unroll
    for (int k = 0; k < K_; k++) {
        float4 v = g_Y4[(size_t)sr[k] * (D_ / 4) + c4];
        acc.x += v.x; acc.y += v.y; acc.z += v.z; acc.w += v.w;
    }
    out[idx] = acc;
}

// ---------------------------------------------------------------------------
extern "C" void kernel_launch(void* const* d_in, const int* in_sizes, int n_in,
                              void* d_out, int out_size) {
    const float* x   = (const float*)d_in[0];
    const float* w0  = (const float*)d_in[1];
    const float* w1  = (const float*)d_in[2];
    const float* w2  = (const float*)d_in[3];
    const float* s0  = (const float*)d_in[4];
    const float* s1  = (const float*)d_in[5];
    const float* s2  = (const float*)d_in[6];
    const void*  sel = (const void*)d_in[7];
    const float* rw  = (const float*)d_in[8];
    float* out = (float*)d_out;

    cudaFuncSetAttribute(gemm1_mma, cudaFuncAttributeMaxDynamicSharedMemorySize, SMEM_BYTES);
    cudaFuncSetAttribute(gemm2_mma, cudaFuncAttributeMaxDynamicSharedMemorySize, SMEM_BYTES);

    setup_kernel<<<1, 256>>>(sel, rw);
    gemm1_mma<<<dim3(DFF_ / 64, MAXTILES), 256, SMEM_BYTES>>>(x, w0, w1, s0, s1);
    gemm2_mma<<<dim3(D_ / 128, MAXTILES), 256, SMEM_BYTES>>>(w2, s2);
    reduce_kernel<<<(T_ * D_ / 4) / 256, 256>>>((float4*)out);
}